// round 5
// baseline (speedup 1.0000x reference)
#include <cuda_runtime.h>

// ---------------------------------------------------------------------------
// manyToManyGRU: B=32, T=128, DIN=DOUT=1024, fp32.
//
// Structure:
//   - One persistent kernel, 128 CTAs x 256 threads, all co-resident
//     (96KB dynamic SMEM/CTA, <=1-2 CTAs/SM; 128 <= 148 SMs).
//   - Phase 0: each CTA computes the x-projections for its 8 output columns
//     (all t,b) with Wz/Wr/Wh slices staged in SMEM; writes to g_gx (global
//     scratch, [g][t][j][b] layout; self-read only, no barrier needed).
//   - Recurrent loop (128 steps, 2 grid barriers/step):
//       phase A: z,r = sigmoid(gx + h @ U{z,r}^T); write rh = r*h (k-packed)
//       phase B: hh  = sigmoid(gx + rh @ Uh^T); h' = h + z*(hh-h); write out+hT
//     h broadcast buffer layout [k/4][b][4] -> one coalesced LDG.128 per 4 k.
//     Cross-SM reads use __ldcg (L1 is not coherent across SMs).
//   - Output layout matches the reference's reshape: memory is (T,B,D).
// ---------------------------------------------------------------------------

#define B_   32
#define T_   128
#define DIN_ 1024
#define D_   1024
#define NCTA 128
#define JPC  8          // output columns per CTA (128*8 = 1024)
#define TPB  256
#define SMEM_BYTES (3*JPC*DIN_*4)   // 96 KB

__device__ float    g_gx[(size_t)3*T_*D_*B_];   // [(g*T+t)*D + j]*B + b  (48 MB)
__device__ float    g_hT[D_*B_];                // packed: ((k>>2)*B + b)*4 + (k&3)
__device__ float    g_rhT[D_*B_];               // same packing
__device__ unsigned g_bar_count = 0;
__device__ unsigned g_bar_gen   = 0;

__device__ __forceinline__ float sigm(float v) { return 1.0f / (1.0f + __expf(-v)); }

// Grid-wide barrier (sense via monotonically increasing generation counter;
// state is self-restoring across graph replays: count returns to 0 each time).
__device__ __forceinline__ void grid_barrier()
{
    __syncthreads();
    if (threadIdx.x == 0) {
        __threadfence();                                   // release our stores
        unsigned gen = *((volatile unsigned*)&g_bar_gen);  // read BEFORE arriving
        __threadfence();                                   // order gen-read < count-RMW
        if (atomicAdd(&g_bar_count, 1u) == NCTA - 1u) {
            g_bar_count = 0u;
            __threadfence();
            atomicAdd(&g_bar_gen, 1u);
        } else {
            while (*((volatile unsigned*)&g_bar_gen) == gen) { }
        }
        __threadfence();                                   // acquire
    }
    __syncthreads();
}

__global__ void __launch_bounds__(TPB, 1)
gru_kernel(const float* __restrict__ x,
           const float* __restrict__ Wz, const float* __restrict__ bz,
           const float* __restrict__ Uz, const float* __restrict__ cz,
           const float* __restrict__ Wr, const float* __restrict__ br,
           const float* __restrict__ Ur, const float* __restrict__ cr,
           const float* __restrict__ Wh, const float* __restrict__ bh,
           const float* __restrict__ Uh, const float* __restrict__ ch,
           float* __restrict__ out)
{
    extern __shared__ float smem[];          // [3][JPC][DIN] weight slices
    __shared__ float sbias[3*JPC];

    const int tid  = threadIdx.x;
    const int w    = tid >> 5;               // warp id 0..7
    const int lane = tid & 31;               // lane = batch b
    const int j0   = blockIdx.x * JPC;

    // ---- stage W{z,r,h} slices into SMEM; fold biases (bg + cg) ----
    for (int i = tid; i < JPC*DIN_; i += TPB) {
        int jj = i >> 10, k = i & (DIN_-1);
        smem[0*JPC*DIN_ + i] = Wz[(j0+jj)*DIN_ + k];
        smem[1*JPC*DIN_ + i] = Wr[(j0+jj)*DIN_ + k];
        smem[2*JPC*DIN_ + i] = Wh[(j0+jj)*DIN_ + k];
    }
    if (tid < 3*JPC) {
        int g = tid / JPC, jj = tid - g*JPC;
        const float* bb = (g==0) ? bz : (g==1) ? br : bh;
        const float* cc = (g==0) ? cz : (g==1) ? cr : ch;
        sbias[tid] = bb[j0+jj] + cc[j0+jj];
    }
    __syncthreads();

    // ---- Phase 0: x-projections. warp w handles t in [16w, 16w+16), lane=b.
    // Each thread keeps 24 accumulators (3 gates x 8 cols) so one x float4
    // feeds 96 FFMAs -> FMA-pipe bound, no cross-warp x replication.
    for (int tt = 0; tt < 16; tt++) {
        const int t = w*16 + tt;
        float acc[3][JPC];
        #pragma unroll
        for (int g = 0; g < 3; g++)
            #pragma unroll
            for (int jj = 0; jj < JPC; jj++) acc[g][jj] = 0.0f;

        const float4* xr = (const float4*)(x + ((size_t)lane*T_ + t)*DIN_);
        for (int kk = 0; kk < DIN_/4; kk++) {
            const float4 xv = __ldg(&xr[kk]);
            #pragma unroll
            for (int g = 0; g < 3; g++) {
                #pragma unroll
                for (int jj = 0; jj < JPC; jj++) {
                    const float4 wv = *(const float4*)&smem[((g*JPC+jj)<<10) + (kk<<2)];
                    float a = acc[g][jj];
                    a = fmaf(xv.x, wv.x, a);
                    a = fmaf(xv.y, wv.y, a);
                    a = fmaf(xv.z, wv.z, a);
                    a = fmaf(xv.w, wv.w, a);
                    acc[g][jj] = a;
                }
            }
        }
        #pragma unroll
        for (int g = 0; g < 3; g++)
            #pragma unroll
            for (int jj = 0; jj < JPC; jj++)
                g_gx[((size_t)(g*T_+t)*D_ + (j0+jj))*B_ + lane] =
                    acc[g][jj] + sbias[g*JPC+jj];
    }
    __syncthreads();   // everyone done reading W before overwrite

    // ---- reload SMEM with U{z,r,h} slices (kept resident for all 128 steps)
    for (int i = tid; i < JPC*DIN_; i += TPB) {
        int jj = i >> 10, k = i & (DIN_-1);
        smem[0*JPC*DIN_ + i] = Uz[(j0+jj)*DIN_ + k];
        smem[1*JPC*DIN_ + i] = Ur[(j0+jj)*DIN_ + k];
        smem[2*JPC*DIN_ + i] = Uh[(j0+jj)*DIN_ + k];
    }

    // zero this CTA's h0 slice (k = j0..j0+7, all b)
    {
        const int k = j0 + w;
        g_hT[(((k>>2)*B_) + lane)*4 + (k&3)] = 0.0f;
    }

    grid_barrier();    // h0 zeros + all U slices visible

    // ---- recurrence: warp = jl (column), lane = b. h[b][j] stays in reg.
    const int jl = w;
    const int b  = lane;
    const int j  = j0 + jl;
    const float4* uzp = (const float4*)&smem[(0*JPC+jl)*DIN_];
    const float4* urp = (const float4*)&smem[(1*JPC+jl)*DIN_];
    const float4* uhp = (const float4*)&smem[(2*JPC+jl)*DIN_];
    const float4* h4  = (const float4*)g_hT;
    const float4* rh4 = (const float4*)g_rhT;
    const int hslot = ((j>>2)*B_ + b)*4 + (j&3);

    float hprev = 0.0f;

    for (int t = 0; t < T_; t++) {
        // ---- phase A: z, r ----
        float4 az = make_float4(0.f,0.f,0.f,0.f);
        float4 ar = make_float4(0.f,0.f,0.f,0.f);
        #pragma unroll 8
        for (int kk = 0; kk < D_/4; kk++) {
            const float4 hv  = __ldcg(&h4[kk*B_ + b]);   // bypass L1 (cross-SM data)
            const float4 wzv = uzp[kk];
            const float4 wrv = urp[kk];
            az.x = fmaf(hv.x, wzv.x, az.x); az.y = fmaf(hv.y, wzv.y, az.y);
            az.z = fmaf(hv.z, wzv.z, az.z); az.w = fmaf(hv.w, wzv.w, az.w);
            ar.x = fmaf(hv.x, wrv.x, ar.x); ar.y = fmaf(hv.y, wrv.y, ar.y);
            ar.z = fmaf(hv.z, wrv.z, ar.z); ar.w = fmaf(hv.w, wrv.w, ar.w);
        }
        const float z = sigm(g_gx[((size_t)(0*T_+t)*D_ + j)*B_ + b] + (az.x+az.y)+(az.z+az.w));
        const float r = sigm(g_gx[((size_t)(1*T_+t)*D_ + j)*B_ + b] + (ar.x+ar.y)+(ar.z+ar.w));
        g_rhT[hslot] = r * hprev;
        grid_barrier();

        // ---- phase B: candidate + state update ----
        float4 ah = make_float4(0.f,0.f,0.f,0.f);
        #pragma unroll 8
        for (int kk = 0; kk < D_/4; kk++) {
            const float4 rv  = __ldcg(&rh4[kk*B_ + b]);
            const float4 whv = uhp[kk];
            ah.x = fmaf(rv.x, whv.x, ah.x); ah.y = fmaf(rv.y, whv.y, ah.y);
            ah.z = fmaf(rv.z, whv.z, ah.z); ah.w = fmaf(rv.w, whv.w, ah.w);
        }
        const float hh = sigm(g_gx[((size_t)(2*T_+t)*D_ + j)*B_ + b] + (ah.x+ah.y)+(ah.z+ah.w));
        const float hn = fmaf(z, hh - hprev, hprev);   // (1-z)h + z*hh
        // reference reshapes (T,B,D)-contiguous scan output to (B,T,D):
        // flat memory layout is (T,B,D).
        out[(size_t)t*(B_*D_) + b*D_ + j] = hn;
        g_hT[hslot] = hn;
        hprev = hn;
        grid_barrier();
    }
}

extern "C" void kernel_launch(void* const* d_in, const int* in_sizes, int n_in,
                              void* d_out, int out_size)
{
    (void)in_sizes; (void)n_in; (void)out_size;
    const float* x  = (const float*)d_in[0];
    const float* Wz = (const float*)d_in[1];
    const float* bz = (const float*)d_in[2];
    const float* Uz = (const float*)d_in[3];
    const float* cz = (const float*)d_in[4];
    const float* Wr = (const float*)d_in[5];
    const float* br = (const float*)d_in[6];
    const float* Ur = (const float*)d_in[7];
    const float* cr = (const float*)d_in[8];
    const float* Wh = (const float*)d_in[9];
    const float* bh = (const float*)d_in[10];
    const float* Uh = (const float*)d_in[11];
    const float* ch = (const float*)d_in[12];
    float* out = (float*)d_out;

    cudaFuncSetAttribute(gru_kernel, cudaFuncAttributeMaxDynamicSharedMemorySize,
                         SMEM_BYTES);
    gru_kernel<<<NCTA, TPB, SMEM_BYTES>>>(x, Wz, bz, Uz, cz, Wr, br, Ur, cr,
                                          Wh, bh, Uh, ch, out);
}

// round 6
// speedup vs baseline: 1.2356x; 1.2356x over previous
#include <cuda_runtime.h>

// ---------------------------------------------------------------------------
// manyToManyGRU: B=32, T=128, DIN=DOUT=1024, fp32.
//
// R5 changes vs R3 (5193us): 512 threads/CTA (16 warps/SM instead of 8) to
// hide L2 latency of the h-broadcast loads; recurrence K-dim split in halves
// across warp pairs with SMEM partial-sum combine. Grid stays 128 CTAs
// (co-resident, grid barrier fan-in unchanged).
// ---------------------------------------------------------------------------

#define B_   32
#define T_   128
#define DIN_ 1024
#define D_   1024
#define NCTA 128
#define JPC  8          // output columns per CTA (128*8 = 1024)
#define TPB  512        // 16 warps
#define SMEM_BYTES (3*JPC*DIN_*4)   // 96 KB dynamic (weight slices)

__device__ float    g_gx[(size_t)3*T_*D_*B_];   // [(g*T+t)*D + j]*B + b
__device__ float    g_hT[D_*B_];                // packed: ((k>>2)*B + b)*4 + (k&3)
__device__ float    g_rhT[D_*B_];               // same packing
__device__ unsigned g_bar_count = 0;
__device__ unsigned g_bar_gen   = 0;

__device__ __forceinline__ float sigm(float v) { return 1.0f / (1.0f + __expf(-v)); }

// Grid-wide barrier (generation counter; state self-restoring across replays).
__device__ __forceinline__ void grid_barrier()
{
    __syncthreads();
    if (threadIdx.x == 0) {
        __threadfence();                                   // release our stores
        unsigned gen = *((volatile unsigned*)&g_bar_gen);  // read BEFORE arriving
        __threadfence();                                   // order gen-read < count-RMW
        if (atomicAdd(&g_bar_count, 1u) == NCTA - 1u) {
            g_bar_count = 0u;
            __threadfence();
            atomicAdd(&g_bar_gen, 1u);
        } else {
            while (*((volatile unsigned*)&g_bar_gen) == gen) { }
        }
        __threadfence();                                   // acquire
    }
    __syncthreads();
}

__global__ void __launch_bounds__(TPB, 1)
gru_kernel(const float* __restrict__ x,
           const float* __restrict__ Wz, const float* __restrict__ bz,
           const float* __restrict__ Uz, const float* __restrict__ cz,
           const float* __restrict__ Wr, const float* __restrict__ br,
           const float* __restrict__ Ur, const float* __restrict__ cr,
           const float* __restrict__ Wh, const float* __restrict__ bh,
           const float* __restrict__ Uh, const float* __restrict__ ch,
           float* __restrict__ out)
{
    extern __shared__ float smem[];          // [3][JPC][DIN] weight slices
    __shared__ float sbias[3*JPC];
    __shared__ float sparA[2][JPC*32];       // phase-A partials from k-half 1
    __shared__ float sparB[JPC*32];          // phase-B partials from k-half 1

    const int tid  = threadIdx.x;
    const int w    = tid >> 5;               // warp id 0..15
    const int lane = tid & 31;               // lane = batch b
    const int j0   = blockIdx.x * JPC;

    // ---- stage W{z,r,h} slices into SMEM; fold biases (bg + cg) ----
    for (int i = tid; i < JPC*DIN_; i += TPB) {
        int jj = i >> 10, k = i & (DIN_-1);
        smem[0*JPC*DIN_ + i] = Wz[(j0+jj)*DIN_ + k];
        smem[1*JPC*DIN_ + i] = Wr[(j0+jj)*DIN_ + k];
        smem[2*JPC*DIN_ + i] = Wh[(j0+jj)*DIN_ + k];
    }
    if (tid < 3*JPC) {
        int g = tid / JPC, jj = tid - g*JPC;
        const float* bb = (g==0) ? bz : (g==1) ? br : bh;
        const float* cc = (g==0) ? cz : (g==1) ? cr : ch;
        sbias[tid] = bb[j0+jj] + cc[j0+jj];
    }
    __syncthreads();

    // ---- Phase 0: x-projections. warp w handles t in [8w, 8w+8), lane=b.
    // 24 accumulators/thread (3 gates x 8 cols): one x float4 -> 96 FFMAs.
    for (int tt = 0; tt < 8; tt++) {
        const int t = w*8 + tt;
        float acc[3][JPC];
        #pragma unroll
        for (int g = 0; g < 3; g++)
            #pragma unroll
            for (int jj = 0; jj < JPC; jj++) acc[g][jj] = 0.0f;

        const float4* xr = (const float4*)(x + ((size_t)lane*T_ + t)*DIN_);
        for (int kk = 0; kk < DIN_/4; kk++) {
            const float4 xv = __ldg(&xr[kk]);
            #pragma unroll
            for (int g = 0; g < 3; g++) {
                #pragma unroll
                for (int jj = 0; jj < JPC; jj++) {
                    const float4 wv = *(const float4*)&smem[((g*JPC+jj)<<10) + (kk<<2)];
                    float a = acc[g][jj];
                    a = fmaf(xv.x, wv.x, a);
                    a = fmaf(xv.y, wv.y, a);
                    a = fmaf(xv.z, wv.z, a);
                    a = fmaf(xv.w, wv.w, a);
                    acc[g][jj] = a;
                }
            }
        }
        #pragma unroll
        for (int g = 0; g < 3; g++)
            #pragma unroll
            for (int jj = 0; jj < JPC; jj++)
                g_gx[((size_t)(g*T_+t)*D_ + (j0+jj))*B_ + lane] =
                    acc[g][jj] + sbias[g*JPC+jj];
    }
    __syncthreads();   // everyone done reading W before overwrite

    // ---- reload SMEM with U{z,r,h} slices (resident for all 128 steps)
    for (int i = tid; i < JPC*DIN_; i += TPB) {
        int jj = i >> 10, k = i & (DIN_-1);
        smem[0*JPC*DIN_ + i] = Uz[(j0+jj)*DIN_ + k];
        smem[1*JPC*DIN_ + i] = Ur[(j0+jj)*DIN_ + k];
        smem[2*JPC*DIN_ + i] = Uh[(j0+jj)*DIN_ + k];
    }

    // zero this CTA's h0 slice (k = j0..j0+7, all b)
    if (tid < JPC*B_) {
        const int k = j0 + (tid >> 5);
        g_hT[(((k>>2)*B_) + (tid & 31))*4 + (k&3)] = 0.0f;
    }

    grid_barrier();    // h0 zeros + all U slices visible

    // ---- recurrence: warp = (jl, k-half). lane = b. 16 warps.
    //   jl = w & 7   -> output column within CTA slice
    //   kh = w >> 3  -> k-half: float4 indices [128*kh, 128*kh+128)
    const int jl = w & 7;
    const int kh = w >> 3;
    const int b  = lane;
    const int j  = j0 + jl;
    const float4* uzp = (const float4*)&smem[(0*JPC+jl)*DIN_] + kh*128;
    const float4* urp = (const float4*)&smem[(1*JPC+jl)*DIN_] + kh*128;
    const float4* uhp = (const float4*)&smem[(2*JPC+jl)*DIN_] + kh*128;
    const float4* h4  = (const float4*)g_hT  + kh*128*B_;
    const float4* rh4 = (const float4*)g_rhT + kh*128*B_;
    const int hslot = ((j>>2)*B_ + b)*4 + (j&3);
    const float* gx0 = g_gx + (size_t)(0*T_)*D_*B_ + (size_t)j*B_ + b;
    const float* gx1 = g_gx + (size_t)(1*T_)*D_*B_ + (size_t)j*B_ + b;
    const float* gx2 = g_gx + (size_t)(2*T_)*D_*B_ + (size_t)j*B_ + b;

    float hprev = 0.0f;    // valid in kh==0 threads
    float zreg  = 0.0f;

    for (int t = 0; t < T_; t++) {
        // ---- phase A: z, r (each warp-pair half does 128 float4 of K) ----
        float4 az = make_float4(0.f,0.f,0.f,0.f);
        float4 ar = make_float4(0.f,0.f,0.f,0.f);
        #pragma unroll 8
        for (int kk = 0; kk < 128; kk++) {
            const float4 hv  = __ldcg(&h4[kk*B_ + b]);   // cross-SM: bypass L1
            const float4 wzv = uzp[kk];
            const float4 wrv = urp[kk];
            az.x = fmaf(hv.x, wzv.x, az.x); az.y = fmaf(hv.y, wzv.y, az.y);
            az.z = fmaf(hv.z, wzv.z, az.z); az.w = fmaf(hv.w, wzv.w, az.w);
            ar.x = fmaf(hv.x, wrv.x, ar.x); ar.y = fmaf(hv.y, wrv.y, ar.y);
            ar.z = fmaf(hv.z, wrv.z, ar.z); ar.w = fmaf(hv.w, wrv.w, ar.w);
        }
        const float azs = (az.x+az.y)+(az.z+az.w);
        const float ars = (ar.x+ar.y)+(ar.z+ar.w);
        if (kh == 1) { sparA[0][jl*32+b] = azs; sparA[1][jl*32+b] = ars; }
        __syncthreads();
        if (kh == 0) {
            const float z = sigm(gx0[(size_t)t*D_*B_] + azs + sparA[0][jl*32+b]);
            const float r = sigm(gx1[(size_t)t*D_*B_] + ars + sparA[1][jl*32+b]);
            zreg = z;
            g_rhT[hslot] = r * hprev;
        }
        grid_barrier();

        // ---- phase B: candidate + state update ----
        float4 ah = make_float4(0.f,0.f,0.f,0.f);
        #pragma unroll 8
        for (int kk = 0; kk < 128; kk++) {
            const float4 rv  = __ldcg(&rh4[kk*B_ + b]);
            const float4 whv = uhp[kk];
            ah.x = fmaf(rv.x, whv.x, ah.x); ah.y = fmaf(rv.y, whv.y, ah.y);
            ah.z = fmaf(rv.z, whv.z, ah.z); ah.w = fmaf(rv.w, whv.w, ah.w);
        }
        const float ahs = (ah.x+ah.y)+(ah.z+ah.w);
        if (kh == 1) sparB[jl*32+b] = ahs;
        __syncthreads();
        if (kh == 0) {
            const float hh = sigm(gx2[(size_t)t*D_*B_] + ahs + sparB[jl*32+b]);
            const float hn = fmaf(zreg, hh - hprev, hprev);
            // reference reshapes (T,B,D)-contiguous scan output to (B,T,D):
            // flat memory layout is (T,B,D).
            out[(size_t)t*(B_*D_) + b*D_ + j] = hn;
            g_hT[hslot] = hn;
            hprev = hn;
        }
        grid_barrier();
    }
}

extern "C" void kernel_launch(void* const* d_in, const int* in_sizes, int n_in,
                              void* d_out, int out_size)
{
    (void)in_sizes; (void)n_in; (void)out_size;
    const float* x  = (const float*)d_in[0];
    const float* Wz = (const float*)d_in[1];
    const float* bz = (const float*)d_in[2];
    const float* Uz = (const float*)d_in[3];
    const float* cz = (const float*)d_in[4];
    const float* Wr = (const float*)d_in[5];
    const float* br = (const float*)d_in[6];
    const float* Ur = (const float*)d_in[7];
    const float* cr = (const float*)d_in[8];
    const float* Wh = (const float*)d_in[9];
    const float* bh = (const float*)d_in[10];
    const float* Uh = (const float*)d_in[11];
    const float* ch = (const float*)d_in[12];
    float* out = (float*)d_out;

    cudaFuncSetAttribute(gru_kernel, cudaFuncAttributeMaxDynamicSharedMemorySize,
                         SMEM_BYTES);
    gru_kernel<<<NCTA, TPB, SMEM_BYTES>>>(x, Wz, bz, Uz, cz, Wr, br, Ur, cr,
                                          Wh, bh, Uh, ch, out);
}

// round 7
// speedup vs baseline: 1.6319x; 1.3207x over previous
#include <cuda_runtime.h>

// ---------------------------------------------------------------------------
// manyToManyGRU: B=32, T=128, DIN=DOUT=1024, fp32.
//
// R6 vs R5 (4203us): recurrence was L2/L1-bandwidth bound (each column-warp
// re-loaded the whole h vector; 32 GB of L2 traffic). Now a warp owns a
// K-chunk and each thread accumulates ALL 8 CTA columns (both gates) from one
// h load -> 8x less h traffic (one full-h read per CTA per phase). Cross-warp
// partials combine via SMEM + 512-thread reduction that also applies the
// sigmoids and the state update (h_prev, z live in SMEM).
// ---------------------------------------------------------------------------

#define B_   32
#define T_   128
#define DIN_ 1024
#define D_   1024
#define NCTA 128
#define JPC  8          // output columns per CTA (128*8 = 1024)
#define TPB  512        // 16 warps
#define NW   16
#define KC   16         // float4 k-chunk per warp (16 warps * 16 * 4 = 1024 k)
#define SMEM_BYTES (3*JPC*DIN_*4)   // 96 KB dynamic (weight slices)

__device__ float    g_gx[(size_t)3*T_*D_*B_];   // [(g*T+t)*D + j]*B + b
__device__ float    g_hT[D_*B_];                // packed: ((k>>2)*B + b)*4 + (k&3)
__device__ float    g_rhT[D_*B_];               // same packing
__device__ unsigned g_bar_count = 0;
__device__ unsigned g_bar_gen   = 0;

__device__ __forceinline__ float sigm(float v) { return 1.0f / (1.0f + __expf(-v)); }

// Grid-wide barrier (generation counter; state self-restoring across replays).
__device__ __forceinline__ void grid_barrier()
{
    __syncthreads();
    if (threadIdx.x == 0) {
        __threadfence();                                   // release our stores
        unsigned gen = *((volatile unsigned*)&g_bar_gen);  // read BEFORE arriving
        __threadfence();                                   // order gen-read < count-RMW
        if (atomicAdd(&g_bar_count, 1u) == NCTA - 1u) {
            g_bar_count = 0u;
            __threadfence();
            atomicAdd(&g_bar_gen, 1u);
        } else {
            while (*((volatile unsigned*)&g_bar_gen) == gen) { }
        }
        __threadfence();                                   // acquire
    }
    __syncthreads();
}

__global__ void __launch_bounds__(TPB, 1)
gru_kernel(const float* __restrict__ x,
           const float* __restrict__ Wz, const float* __restrict__ bz,
           const float* __restrict__ Uz, const float* __restrict__ cz,
           const float* __restrict__ Wr, const float* __restrict__ br,
           const float* __restrict__ Ur, const float* __restrict__ cr,
           const float* __restrict__ Wh, const float* __restrict__ bh,
           const float* __restrict__ Uh, const float* __restrict__ ch,
           float* __restrict__ out)
{
    extern __shared__ float smem[];          // [3][JPC][DIN] weight slices
    __shared__ float sbias[3*JPC];
    __shared__ float spar[2][NW*256];        // partials: [gate][w*256 + b*8 + jj]
    __shared__ float sh_z[256];              // [b*8 + jj]
    __shared__ float sh_h[256];              // [b*8 + jj]  (h_prev)

    const int tid  = threadIdx.x;
    const int w    = tid >> 5;               // warp id 0..15
    const int lane = tid & 31;               // lane = batch b
    const int j0   = blockIdx.x * JPC;

    // ---- stage W{z,r,h} slices into SMEM; fold biases (bg + cg) ----
    for (int i = tid; i < JPC*DIN_; i += TPB) {
        int jj = i >> 10, k = i & (DIN_-1);
        smem[0*JPC*DIN_ + i] = Wz[(j0+jj)*DIN_ + k];
        smem[1*JPC*DIN_ + i] = Wr[(j0+jj)*DIN_ + k];
        smem[2*JPC*DIN_ + i] = Wh[(j0+jj)*DIN_ + k];
    }
    if (tid < 3*JPC) {
        int g = tid / JPC, jj = tid - g*JPC;
        const float* bb = (g==0) ? bz : (g==1) ? br : bh;
        const float* cc = (g==0) ? cz : (g==1) ? cr : ch;
        sbias[tid] = bb[j0+jj] + cc[j0+jj];
    }
    __syncthreads();

    // ---- Phase 0: x-projections. warp w handles t in [8w, 8w+8), lane=b.
    for (int tt = 0; tt < 8; tt++) {
        const int t = w*8 + tt;
        float acc[3][JPC];
        #pragma unroll
        for (int g = 0; g < 3; g++)
            #pragma unroll
            for (int jj = 0; jj < JPC; jj++) acc[g][jj] = 0.0f;

        const float4* xr = (const float4*)(x + ((size_t)lane*T_ + t)*DIN_);
        for (int kk = 0; kk < DIN_/4; kk++) {
            const float4 xv = __ldg(&xr[kk]);
            #pragma unroll
            for (int g = 0; g < 3; g++) {
                #pragma unroll
                for (int jj = 0; jj < JPC; jj++) {
                    const float4 wv = *(const float4*)&smem[((g*JPC+jj)<<10) + (kk<<2)];
                    float a = acc[g][jj];
                    a = fmaf(xv.x, wv.x, a);
                    a = fmaf(xv.y, wv.y, a);
                    a = fmaf(xv.z, wv.z, a);
                    a = fmaf(xv.w, wv.w, a);
                    acc[g][jj] = a;
                }
            }
        }
        #pragma unroll
        for (int g = 0; g < 3; g++)
            #pragma unroll
            for (int jj = 0; jj < JPC; jj++)
                g_gx[((size_t)(g*T_+t)*D_ + (j0+jj))*B_ + lane] =
                    acc[g][jj] + sbias[g*JPC+jj];
    }
    __syncthreads();   // everyone done reading W before overwrite

    // ---- reload SMEM with U{z,r,h} slices (resident for all 128 steps)
    for (int i = tid; i < JPC*DIN_; i += TPB) {
        int jj = i >> 10, k = i & (DIN_-1);
        smem[0*JPC*DIN_ + i] = Uz[(j0+jj)*DIN_ + k];
        smem[1*JPC*DIN_ + i] = Ur[(j0+jj)*DIN_ + k];
        smem[2*JPC*DIN_ + i] = Uh[(j0+jj)*DIN_ + k];
    }

    // zero this CTA's h0 slice in global; zero sh_h locally
    if (tid < JPC*B_) {
        const int k = j0 + (tid >> 5);
        g_hT[(((k>>2)*B_) + (tid & 31))*4 + (k&3)] = 0.0f;
    }
    if (tid < 256) sh_h[tid] = 0.0f;

    grid_barrier();    // h0 zeros + all U slices visible (+ local syncthreads)

    // ---- recurrence: warp w owns k-chunk [w*KC, w*KC+KC) of float4 indices.
    // Each thread accumulates all 8 CTA columns from each h float4 it loads.
    const int k4b = w * KC;
    const int b   = lane;
    const float4* h4  = (const float4*)g_hT;
    const float4* rh4 = (const float4*)g_rhT;

    for (int t = 0; t < T_; t++) {
        // ================= phase A: z, r =================
        float az[JPC], ar[JPC];
        #pragma unroll
        for (int jj = 0; jj < JPC; jj++) { az[jj] = 0.0f; ar[jj] = 0.0f; }

        #pragma unroll 4
        for (int kk = 0; kk < KC; kk++) {
            const float4 hv = __ldcg(&h4[(k4b+kk)*B_ + b]);
            #pragma unroll
            for (int jj = 0; jj < JPC; jj++) {
                const float4 wz = *(const float4*)&smem[(0*JPC+jj)*DIN_ + ((k4b+kk)<<2)];
                const float4 wr = *(const float4*)&smem[(1*JPC+jj)*DIN_ + ((k4b+kk)<<2)];
                float a = az[jj];
                a = fmaf(hv.x, wz.x, a); a = fmaf(hv.y, wz.y, a);
                a = fmaf(hv.z, wz.z, a); a = fmaf(hv.w, wz.w, a);
                az[jj] = a;
                float c = ar[jj];
                c = fmaf(hv.x, wr.x, c); c = fmaf(hv.y, wr.y, c);
                c = fmaf(hv.z, wr.z, c); c = fmaf(hv.w, wr.w, c);
                ar[jj] = c;
            }
        }
        // store partials as float4 (layout [g][w*256 + b*8 + jj])
        {
            float4* pz = (float4*)&spar[0][w*256 + b*8];
            float4* pr = (float4*)&spar[1][w*256 + b*8];
            pz[0] = make_float4(az[0], az[1], az[2], az[3]);
            pz[1] = make_float4(az[4], az[5], az[6], az[7]);
            pr[0] = make_float4(ar[0], ar[1], ar[2], ar[3]);
            pr[1] = make_float4(ar[4], ar[5], ar[6], ar[7]);
        }
        __syncthreads();
        // reduction: 512 threads -> 2 gates x 8 jj x 32 b outputs
        {
            const int g  = tid >> 8;        // 0 = z, 1 = r
            const int i  = tid & 255;       // b*8 + jj
            const int jj = i & 7;
            const int bb = i >> 3;
            const int j  = j0 + jj;
            float s = g_gx[((size_t)(g*T_+t)*D_ + j)*B_ + bb];
            #pragma unroll
            for (int w2 = 0; w2 < NW; w2++) s += spar[g][w2*256 + i];
            const float v = sigm(s);
            if (g == 0) sh_z[i] = v;
            else        g_rhT[((j>>2)*B_ + bb)*4 + (j&3)] = v * sh_h[i];
        }
        grid_barrier();

        // ================= phase B: candidate + update =================
        float ah[JPC];
        #pragma unroll
        for (int jj = 0; jj < JPC; jj++) ah[jj] = 0.0f;

        #pragma unroll 4
        for (int kk = 0; kk < KC; kk++) {
            const float4 rv = __ldcg(&rh4[(k4b+kk)*B_ + b]);
            #pragma unroll
            for (int jj = 0; jj < JPC; jj++) {
                const float4 wh = *(const float4*)&smem[(2*JPC+jj)*DIN_ + ((k4b+kk)<<2)];
                float a = ah[jj];
                a = fmaf(rv.x, wh.x, a); a = fmaf(rv.y, wh.y, a);
                a = fmaf(rv.z, wh.z, a); a = fmaf(rv.w, wh.w, a);
                ah[jj] = a;
            }
        }
        {
            float4* ph = (float4*)&spar[0][w*256 + b*8];
            ph[0] = make_float4(ah[0], ah[1], ah[2], ah[3]);
            ph[1] = make_float4(ah[4], ah[5], ah[6], ah[7]);
        }
        __syncthreads();
        if (tid < 256) {
            const int jj = tid & 7;
            const int bb = tid >> 3;
            const int j  = j0 + jj;
            float s = g_gx[((size_t)(2*T_+t)*D_ + j)*B_ + bb];
            #pragma unroll
            for (int w2 = 0; w2 < NW; w2++) s += spar[0][w2*256 + tid];
            const float hh   = sigm(s);
            const float hold = sh_h[tid];
            const float hn   = fmaf(sh_z[tid], hh - hold, hold);
            // reference reshape: flat output memory layout is (T,B,D)
            out[(size_t)t*(B_*D_) + bb*D_ + j] = hn;
            g_hT[((j>>2)*B_ + bb)*4 + (j&3)] = hn;
            sh_h[tid] = hn;
        }
        grid_barrier();
    }
}

extern "C" void kernel_launch(void* const* d_in, const int* in_sizes, int n_in,
                              void* d_out, int out_size)
{
    (void)in_sizes; (void)n_in; (void)out_size;
    const float* x  = (const float*)d_in[0];
    const float* Wz = (const float*)d_in[1];
    const float* bz = (const float*)d_in[2];
    const float* Uz = (const float*)d_in[3];
    const float* cz = (const float*)d_in[4];
    const float* Wr = (const float*)d_in[5];
    const float* br = (const float*)d_in[6];
    const float* Ur = (const float*)d_in[7];
    const float* cr = (const float*)d_in[8];
    const float* Wh = (const float*)d_in[9];
    const float* bh = (const float*)d_in[10];
    const float* Uh = (const float*)d_in[11];
    const float* ch = (const float*)d_in[12];
    float* out = (float*)d_out;

    cudaFuncSetAttribute(gru_kernel, cudaFuncAttributeMaxDynamicSharedMemorySize,
                         SMEM_BYTES);
    gru_kernel<<<NCTA, TPB, SMEM_BYTES>>>(x, Wz, bz, Uz, cz, Wr, br, Ur, cr,
                                          Wh, bh, Uh, ch, out);
}

// round 9
// speedup vs baseline: 2.4498x; 1.5012x over previous
#include <cuda_runtime.h>
#include <cuda_bf16.h>
#include <cstdint>

// ---------------------------------------------------------------------------
// manyToManyGRU: B=32, T=128, DIN=DOUT=1024, fp32.
//
// R8 vs R7 (compile fail): toolchain emits baseline compute_103 PTX, so
// tcgen05 is unavailable. The x-projection GEMM now uses warp-level
// mma.sync.m16n8k16 bf16 (sm_80+ baseline PTX -> HMMA SASS) with a 3-way
// fp32 hi/lo split (hi*hi + hi*lo + lo*hi). Everything else as R7:
//   1) split kernel: W{z,r,h}, x -> bf16 (hi,lo) planes
//   2) mma.sync GEMM: gx[3072,4096] = W·x^T, bias folded, layout [g][t][b][j]
//   3) persistent recurrence kernel (R6 structure + gx register prefetch)
// ---------------------------------------------------------------------------

#define B_   32
#define T_   128
#define D_   1024
#define NCTA 128
#define JPC  8
#define TPB  512
#define NW   16
#define KC   16
#define U_SMEM_BYTES (3*JPC*D_*4)   // 96 KB

// gx layout: [(g*T + t)*B + b]*D + j
__device__ __align__(16) float g_gx[(size_t)3*T_*B_*D_];
__device__ __align__(16) float g_hT[D_*B_];     // ((k>>2)*B + b)*4 + (k&3)
__device__ __align__(16) float g_rhT[D_*B_];
__device__ unsigned g_bar_count = 0;
__device__ unsigned g_bar_gen   = 0;

// bf16 split planes
__device__ __align__(16) __nv_bfloat16 g_Wb[2][(size_t)3*D_*D_];  // [part][(g*1024+j)*1024+k]
__device__ __align__(16) __nv_bfloat16 g_xb[2][(size_t)B_*T_*D_]; // [part][(b*T+t)*1024+k]

__device__ __forceinline__ float sigm(float v) { return 1.0f / (1.0f + __expf(-v)); }

__device__ __forceinline__ uint32_t smem_to_u32(const void* p) {
    uint32_t a;
    asm("{ .reg .u64 t; cvta.to.shared.u64 t, %1; cvt.u32.u64 %0, t; }"
        : "=r"(a) : "l"(p));
    return a;
}
__device__ __forceinline__ void ldsm4(uint32_t* r, uint32_t a) {
    asm volatile("ldmatrix.sync.aligned.m8n8.x4.shared.b16 {%0,%1,%2,%3}, [%4];"
        : "=r"(r[0]), "=r"(r[1]), "=r"(r[2]), "=r"(r[3]) : "r"(a));
}
__device__ __forceinline__ void ldsm2(uint32_t* r, uint32_t a) {
    asm volatile("ldmatrix.sync.aligned.m8n8.x2.shared.b16 {%0,%1}, [%2];"
        : "=r"(r[0]), "=r"(r[1]) : "r"(a));
}
__device__ __forceinline__ void mma16816(float* c, const uint32_t* a, const uint32_t* b) {
    asm volatile("mma.sync.aligned.m16n8k16.row.col.f32.bf16.bf16.f32 "
        "{%0,%1,%2,%3}, {%4,%5,%6,%7}, {%8,%9}, {%0,%1,%2,%3};"
        : "+f"(c[0]), "+f"(c[1]), "+f"(c[2]), "+f"(c[3])
        : "r"(a[0]), "r"(a[1]), "r"(a[2]), "r"(a[3]), "r"(b[0]), "r"(b[1]));
}

// ===================== kernel 1: fp32 -> bf16 (hi,lo) split =====================
__global__ void split_kernel(const float* __restrict__ src, int which,
                             size_t off, int n)
{
    __nv_bfloat16* hi = (which ? g_xb[0] : g_Wb[0]) + off;
    __nv_bfloat16* lo = (which ? g_xb[1] : g_Wb[1]) + off;
    for (int i = blockIdx.x*blockDim.x + threadIdx.x; i < n;
         i += gridDim.x*blockDim.x) {
        float v = src[i];
        __nv_bfloat16 h = __float2bfloat16(v);
        hi[i] = h;
        lo[i] = __float2bfloat16(v - __bfloat162float(h));
    }
}

// ===================== kernel 2: mma.sync GEMM for gx =====================
// gx[m, n] = sum_k W[m,k] * x[n,k];  m = g*1024 + j (3072), n = b*T + t (4096).
// CTA tile 128m x 128n, K staged 32 at a time. 8 warps: warp tile 64m x 32n.
#define GM_THREADS 256
#define ASTRIDE 40                      // padded SMEM row stride (bf16 elems)
#define PLANE   (128*ASTRIDE)           // elems per plane
#define GEMM_SMEM (4*PLANE*2)           // Ahi, Alo, Bhi, Blo = 40960 B

__global__ void __launch_bounds__(GM_THREADS, 2)
gemm_kernel(const float* __restrict__ bz, const float* __restrict__ cz,
            const float* __restrict__ br, const float* __restrict__ cr,
            const float* __restrict__ bh, const float* __restrict__ ch)
{
    extern __shared__ __nv_bfloat16 sm[];
    const int tid  = threadIdx.x;
    const int w    = tid >> 5;
    const int lane = tid & 31;
    const int wm   = w >> 2;            // 0..1
    const int wn   = w & 3;             // 0..3
    const int mbase = blockIdx.y * 128; // m tile (24)
    const int nbase = blockIdx.x * 128; // n tile (32)
    const uint32_t smb = smem_to_u32(sm);

    float acc[4][4][4];
    #pragma unroll
    for (int mf = 0; mf < 4; mf++)
        #pragma unroll
        for (int nf = 0; nf < 4; nf++)
            #pragma unroll
            for (int i = 0; i < 4; i++) acc[mf][nf][i] = 0.0f;

    for (int kc = 0; kc < 32; kc++) {
        // stage Ahi/Alo/Bhi/Blo 128x32 tiles -> SMEM (2048 uint4, 8/thread)
        #pragma unroll
        for (int it = 0; it < 8; it++) {
            const int idx  = tid + it * GM_THREADS;
            const int part = idx >> 9;          // 0 Ahi, 1 Alo, 2 Bhi, 3 Blo
            const int rem  = idx & 511;
            const int row  = rem >> 2;
            const int chk  = rem & 3;
            const uint4* src = (part < 2)
                ? (const uint4*)&g_Wb[part    ][((size_t)(mbase + row) << 10) + kc*32 + chk*8]
                : (const uint4*)&g_xb[part - 2][((size_t)(nbase + row) << 10) + kc*32 + chk*8];
            *(uint4*)&sm[part*PLANE + row*ASTRIDE + chk*8] = __ldg(src);
        }
        __syncthreads();

        #pragma unroll
        for (int h = 0; h < 2; h++) {
            const int k16 = h * 16;
            uint32_t af[4][4], bhf[4][2], blf[4][2];
            #pragma unroll
            for (int mf = 0; mf < 4; mf++) {
                const uint32_t a = smb + 2u*(0*PLANE +
                    (wm*64 + mf*16 + (lane & 15))*ASTRIDE + k16 + (lane >> 4)*8);
                ldsm4(af[mf], a);
            }
            #pragma unroll
            for (int nf = 0; nf < 4; nf++) {
                const uint32_t rc = (wn*32 + nf*8 + (lane & 7))*ASTRIDE + k16 + ((lane >> 3) & 1)*8;
                ldsm2(bhf[nf], smb + 2u*(2*PLANE + rc));
                ldsm2(blf[nf], smb + 2u*(3*PLANE + rc));
            }
            #pragma unroll
            for (int mf = 0; mf < 4; mf++)
                #pragma unroll
                for (int nf = 0; nf < 4; nf++) {
                    mma16816(acc[mf][nf], af[mf], bhf[nf]);   // hi*hi
                    mma16816(acc[mf][nf], af[mf], blf[nf]);   // hi*lo
                }
            #pragma unroll
            for (int mf = 0; mf < 4; mf++) {
                const uint32_t a = smb + 2u*(1*PLANE +
                    (wm*64 + mf*16 + (lane & 15))*ASTRIDE + k16 + (lane >> 4)*8);
                ldsm4(af[mf], a);                             // Alo
            }
            #pragma unroll
            for (int mf = 0; mf < 4; mf++)
                #pragma unroll
                for (int nf = 0; nf < 4; nf++)
                    mma16816(acc[mf][nf], af[mf], bhf[nf]);   // lo*hi
        }
        __syncthreads();
    }

    // epilogue: fold bias, write gx[(g*T+t)*B+b]*D + j  (g constant per CTA)
    const int g = mbase >> 10;
    const float* bp = (g == 0) ? bz : (g == 1) ? br : bh;
    const float* cp = (g == 0) ? cz : (g == 1) ? cr : ch;
    #pragma unroll
    for (int mf = 0; mf < 4; mf++) {
        const int row0 = wm*64 + mf*16 + (lane >> 2);
        const int jl0  = (mbase + row0) & 1023;
        const int jl8  = (mbase + row0 + 8) & 1023;
        const float bias0 = bp[jl0] + cp[jl0];
        const float bias8 = bp[jl8] + cp[jl8];
        #pragma unroll
        for (int nf = 0; nf < 4; nf++) {
            const int col0 = wn*32 + nf*8 + (lane & 3)*2;
            #pragma unroll
            for (int cc = 0; cc < 2; cc++) {
                const int n = nbase + col0 + cc;
                const int b = n >> 7;               // T = 128
                const int t = n & 127;
                const size_t base = ((size_t)(g*T_ + t)*B_ + b)*D_;
                g_gx[base + jl0] = acc[mf][nf][cc]     + bias0;
                g_gx[base + jl8] = acc[mf][nf][cc + 2] + bias8;
            }
        }
    }
}

// ===================== kernel 3: persistent recurrence =====================
__device__ __forceinline__ void grid_barrier()
{
    __syncthreads();
    if (threadIdx.x == 0) {
        __threadfence();
        unsigned gen = *((volatile unsigned*)&g_bar_gen);
        __threadfence();
        if (atomicAdd(&g_bar_count, 1u) == NCTA - 1u) {
            g_bar_count = 0u;
            __threadfence();
            atomicAdd(&g_bar_gen, 1u);
        } else {
            while (*((volatile unsigned*)&g_bar_gen) == gen) { }
        }
        __threadfence();
    }
    __syncthreads();
}

__global__ void __launch_bounds__(TPB, 1)
gru_kernel(const float* __restrict__ Uz, const float* __restrict__ Ur,
           const float* __restrict__ Uh, float* __restrict__ out)
{
    extern __shared__ float smem[];          // [3][JPC][D] U slices (96 KB)
    __shared__ float spar[2][NW*256];
    __shared__ float sh_z[256];
    __shared__ float sh_h[256];

    const int tid  = threadIdx.x;
    const int w    = tid >> 5;
    const int lane = tid & 31;
    const int j0   = blockIdx.x * JPC;

    for (int i = tid; i < JPC*D_; i += TPB) {
        int jj = i >> 10, k = i & (D_-1);
        smem[0*JPC*D_ + i] = Uz[(j0+jj)*D_ + k];
        smem[1*JPC*D_ + i] = Ur[(j0+jj)*D_ + k];
        smem[2*JPC*D_ + i] = Uh[(j0+jj)*D_ + k];
    }
    if (tid < JPC*B_) {
        const int k = j0 + (tid >> 5);
        g_hT[(((k>>2)*B_) + (tid & 31))*4 + (k&3)] = 0.0f;
    }
    if (tid < 256) sh_h[tid] = 0.0f;

    grid_barrier();

    const int k4b = w * KC;
    const int b   = lane;
    const float4* h4  = (const float4*)g_hT;
    const float4* rh4 = (const float4*)g_rhT;

    const int rg  = tid >> 8;          // 0=z-gate, 1=r-gate
    const int ri  = tid & 255;
    const int rjj = ri & 7;
    const int rbb = ri >> 3;
    const int rj  = j0 + rjj;

    for (int t = 0; t < T_; t++) {
        const float gxA = g_gx[((size_t)(rg*T_ + t)*B_ + rbb)*D_ + rj];
        const float gxB = g_gx[((size_t)(2 *T_ + t)*B_ + rbb)*D_ + rj];

        // ===== phase A: z, r =====
        float az[JPC], ar[JPC];
        #pragma unroll
        for (int jj = 0; jj < JPC; jj++) { az[jj] = 0.0f; ar[jj] = 0.0f; }

        #pragma unroll 4
        for (int kk = 0; kk < KC; kk++) {
            const float4 hv = __ldcg(&h4[(k4b+kk)*B_ + b]);
            #pragma unroll
            for (int jj = 0; jj < JPC; jj++) {
                const float4 wz = *(const float4*)&smem[(0*JPC+jj)*D_ + ((k4b+kk)<<2)];
                const float4 wr = *(const float4*)&smem[(1*JPC+jj)*D_ + ((k4b+kk)<<2)];
                float a = az[jj];
                a = fmaf(hv.x, wz.x, a); a = fmaf(hv.y, wz.y, a);
                a = fmaf(hv.z, wz.z, a); a = fmaf(hv.w, wz.w, a);
                az[jj] = a;
                float c = ar[jj];
                c = fmaf(hv.x, wr.x, c); c = fmaf(hv.y, wr.y, c);
                c = fmaf(hv.z, wr.z, c); c = fmaf(hv.w, wr.w, c);
                ar[jj] = c;
            }
        }
        {
            float4* pz = (float4*)&spar[0][w*256 + b*8];
            float4* pr = (float4*)&spar[1][w*256 + b*8];
            pz[0] = make_float4(az[0], az[1], az[2], az[3]);
            pz[1] = make_float4(az[4], az[5], az[6], az[7]);
            pr[0] = make_float4(ar[0], ar[1], ar[2], ar[3]);
            pr[1] = make_float4(ar[4], ar[5], ar[6], ar[7]);
        }
        __syncthreads();
        {
            float s = gxA;
            #pragma unroll
            for (int w2 = 0; w2 < NW; w2++) s += spar[rg][w2*256 + ri];
            const float v = sigm(s);
            if (rg == 0) sh_z[ri] = v;
            else         g_rhT[((rj>>2)*B_ + rbb)*4 + (rj&3)] = v * sh_h[ri];
        }
        grid_barrier();

        // ===== phase B: candidate + update =====
        float ah[JPC];
        #pragma unroll
        for (int jj = 0; jj < JPC; jj++) ah[jj] = 0.0f;

        #pragma unroll 4
        for (int kk = 0; kk < KC; kk++) {
            const float4 rv = __ldcg(&rh4[(k4b+kk)*B_ + b]);
            #pragma unroll
            for (int jj = 0; jj < JPC; jj++) {
                const float4 wh = *(const float4*)&smem[(2*JPC+jj)*D_ + ((k4b+kk)<<2)];
                float a = ah[jj];
                a = fmaf(rv.x, wh.x, a); a = fmaf(rv.y, wh.y, a);
                a = fmaf(rv.z, wh.z, a); a = fmaf(rv.w, wh.w, a);
                ah[jj] = a;
            }
        }
        {
            float4* ph = (float4*)&spar[0][w*256 + b*8];
            ph[0] = make_float4(ah[0], ah[1], ah[2], ah[3]);
            ph[1] = make_float4(ah[4], ah[5], ah[6], ah[7]);
        }
        __syncthreads();
        if (tid < 256) {
            float s = gxB;
            #pragma unroll
            for (int w2 = 0; w2 < NW; w2++) s += spar[0][w2*256 + tid];
            const float hh   = sigm(s);
            const float hold = sh_h[tid];
            const float hn   = fmaf(sh_z[tid], hh - hold, hold);
            // reference reshape: flat output memory layout is (T,B,D)
            out[(size_t)t*(B_*D_) + rbb*D_ + rj] = hn;
            g_hT[((rj>>2)*B_ + rbb)*4 + (rj&3)] = hn;
            sh_h[tid] = hn;
        }
        grid_barrier();
    }
}

// ===================== launch =====================
extern "C" void kernel_launch(void* const* d_in, const int* in_sizes, int n_in,
                              void* d_out, int out_size)
{
    (void)in_sizes; (void)n_in; (void)out_size;
    const float* x  = (const float*)d_in[0];
    const float* Wz = (const float*)d_in[1];
    const float* bz = (const float*)d_in[2];
    const float* Uz = (const float*)d_in[3];
    const float* cz = (const float*)d_in[4];
    const float* Wr = (const float*)d_in[5];
    const float* br = (const float*)d_in[6];
    const float* Ur = (const float*)d_in[7];
    const float* cr = (const float*)d_in[8];
    const float* Wh = (const float*)d_in[9];
    const float* bh = (const float*)d_in[10];
    const float* Uh = (const float*)d_in[11];
    const float* ch = (const float*)d_in[12];
    float* out = (float*)d_out;

    // 1) bf16 hi/lo splits
    split_kernel<<<256, 256>>>(Wz, 0, (size_t)0,        D_*D_);
    split_kernel<<<256, 256>>>(Wr, 0, (size_t)D_*D_,    D_*D_);
    split_kernel<<<256, 256>>>(Wh, 0, (size_t)2*D_*D_,  D_*D_);
    split_kernel<<<512, 256>>>(x,  1, (size_t)0,        B_*T_*D_);

    // 2) mma.sync GEMM -> g_gx (+bias)
    cudaFuncSetAttribute(gemm_kernel, cudaFuncAttributeMaxDynamicSharedMemorySize,
                         GEMM_SMEM);
    gemm_kernel<<<dim3(32, 24), GM_THREADS, GEMM_SMEM>>>(bz, cz, br, cr, bh, ch);

    // 3) persistent recurrence
    cudaFuncSetAttribute(gru_kernel, cudaFuncAttributeMaxDynamicSharedMemorySize,
                         U_SMEM_BYTES);
    gru_kernel<<<NCTA, TPB, U_SMEM_BYTES>>>(Uz, Ur, Uh, out);
}